// round 16
// baseline (speedup 1.0000x reference)
#include <cuda_runtime.h>
#include <cuda_fp16.h>
#include <stdint.h>

#define NN   100000
#define NE   3200000
#define HID  128
#define ELLW 96      // ELL row width; P(deg >= 96) ~ 1e-18 for Poisson(32)
#define NB   8       // rows per warp in k_gemm tile load

// ---- device scratch ----
__device__ int    g_cnt[NN];           // in-degree; re-zeroed by k_gather each replay
__device__ float  g_dis[NN];           // (deg+1)^{-1/2}
__device__ int    g_ell[NN * ELLW];    // ELL neighbor lists (src ids)
__device__ float  g_xs4[NN * 4];       // {dis*x0, dis*x1, dis*x2, 0}
__device__ __half g_h1h[NN * HID];     // fp16: dis[i] * relu(layer1)
__device__ __half g_aggh[NN * HID];    // fp16 layer-2 aggregate

// ---------------- launch 0: single-pass ELL scatter, 4 edges/thread ----------------

__global__ void k_scat(const int* __restrict__ ei, int E) {
    int e = (blockIdx.x * blockDim.x + threadIdx.x) * 4;
    if (e + 3 < E) {
        int4 s4 = *(const int4*)&ei[e];
        int4 d4 = *(const int4*)&ei[E + e];
        int p0 = atomicAdd(&g_cnt[d4.x], 1);
        if (p0 < ELLW) g_ell[d4.x * ELLW + p0] = s4.x;
        int p1 = atomicAdd(&g_cnt[d4.y], 1);
        if (p1 < ELLW) g_ell[d4.y * ELLW + p1] = s4.y;
        int p2 = atomicAdd(&g_cnt[d4.z], 1);
        if (p2 < ELLW) g_ell[d4.z * ELLW + p2] = s4.z;
        int p3 = atomicAdd(&g_cnt[d4.w], 1);
        if (p3 < ELLW) g_ell[d4.w * ELLW + p3] = s4.w;
    } else {
        for (; e < E; e++) {
            int d = ei[E + e];
            int pos = atomicAdd(&g_cnt[d], 1);
            if (pos < ELLW) g_ell[d * ELLW + pos] = ei[e];
        }
    }
}

// ---------------- launch 1: dis + xs4 ----------------

__global__ void k_prep(const float* __restrict__ x, int n) {
    int i = blockIdx.x * blockDim.x + threadIdx.x;
    if (i < n) {
        float dis = rsqrtf((float)(min(g_cnt[i], ELLW) + 1));
        g_dis[i] = dis;
        float4 v;
        v.x = dis * x[3 * i + 0];
        v.y = dis * x[3 * i + 1];
        v.z = dis * x[3 * i + 2];
        v.w = 0.f;
        *(float4*)&g_xs4[4 * i] = v;
    }
}

// ---------------- launch 2: fused layer-1 agg (warp-per-node, 3 parallel loads) + GEMM ----------------

__global__ void __launch_bounds__(256)
k_aggl1(const float* __restrict__ W1, const float* __restrict__ b1, int n) {
    __shared__ float W1s[3 * HID];
    __shared__ float b1s[HID];
    int tid = threadIdx.x;
    for (int i = tid; i < 3 * HID; i += 256) W1s[i] = W1[i];
    for (int i = tid; i < HID; i += 256) b1s[i] = b1[i];
    __syncthreads();

    int warp = tid >> 5;
    int lane = tid & 31;
    int d = blockIdx.x * 8 + warp;
    if (d >= n) return;

    int base = d * ELLW;
    int nb = min(g_cnt[d], ELLW);
    float sx = 0.f, sy = 0.f, sz = 0.f;
    // ELLW/32 = 3 predicated independent loads, all in flight at once
    #pragma unroll
    for (int t = 0; t < ELLW / 32; t++) {
        int idx = lane + t * 32;
        if (idx < nb) {
            int s = g_ell[base + idx];
            float4 v = *(const float4*)&g_xs4[4 * s];
            sx += v.x; sy += v.y; sz += v.z;
        }
    }
    #pragma unroll
    for (int o = 16; o > 0; o >>= 1) {
        sx += __shfl_xor_sync(0xffffffffu, sx, o);
        sy += __shfl_xor_sync(0xffffffffu, sy, o);
        sz += __shfl_xor_sync(0xffffffffu, sz, o);
    }
    float4 self = *(const float4*)&g_xs4[4 * d];
    float dis = g_dis[d];
    float a0 = (sx + self.x) * dis;
    float a1 = (sy + self.y) * dis;
    float a2 = (sz + self.z) * dis;

    int c = lane * 4;
    float4 o4;
    o4.x = fmaxf(a0 * W1s[c + 0] + a1 * W1s[HID + c + 0] + a2 * W1s[2 * HID + c + 0] + b1s[c + 0], 0.f) * dis;
    o4.y = fmaxf(a0 * W1s[c + 1] + a1 * W1s[HID + c + 1] + a2 * W1s[2 * HID + c + 1] + b1s[c + 1], 0.f) * dis;
    o4.z = fmaxf(a0 * W1s[c + 2] + a1 * W1s[HID + c + 2] + a2 * W1s[2 * HID + c + 2] + b1s[c + 2], 0.f) * dis;
    o4.w = fmaxf(a0 * W1s[c + 3] + a1 * W1s[HID + c + 3] + a2 * W1s[2 * HID + c + 3] + b1s[c + 3], 0.f) * dis;
    __half2 h0 = __floats2half2_rn(o4.x, o4.y);
    __half2 h1 = __floats2half2_rn(o4.z, o4.w);
    uint2 u;
    u.x = *(unsigned*)&h0;
    u.y = *(unsigned*)&h1;
    *(uint2*)&g_h1h[d * HID + c] = u;
}

// ---------------- launch 3: layer-2 gather (warp-per-node, HADD2 tree-8, idx prefetch) ----------------

__device__ __forceinline__ __half2 h2of(uint32_t w) { return *(__half2*)&w; }

__device__ __forceinline__ void gat8(float4& acc, int4 sa, int4 sb, int c) {
    uint2 r0 = *(const uint2*)&g_h1h[sa.x * HID + c];
    uint2 r1 = *(const uint2*)&g_h1h[sa.y * HID + c];
    uint2 r2 = *(const uint2*)&g_h1h[sa.z * HID + c];
    uint2 r3 = *(const uint2*)&g_h1h[sa.w * HID + c];
    uint2 r4 = *(const uint2*)&g_h1h[sb.x * HID + c];
    uint2 r5 = *(const uint2*)&g_h1h[sb.y * HID + c];
    uint2 r6 = *(const uint2*)&g_h1h[sb.z * HID + c];
    uint2 r7 = *(const uint2*)&g_h1h[sb.w * HID + c];
    // tree-8 fp16 partial sums (3 roundings/elem before fp32)
    __half2 tx = __hadd2(
        __hadd2(__hadd2(h2of(r0.x), h2of(r1.x)), __hadd2(h2of(r2.x), h2of(r3.x))),
        __hadd2(__hadd2(h2of(r4.x), h2of(r5.x)), __hadd2(h2of(r6.x), h2of(r7.x))));
    __half2 ty = __hadd2(
        __hadd2(__hadd2(h2of(r0.y), h2of(r1.y)), __hadd2(h2of(r2.y), h2of(r3.y))),
        __hadd2(__hadd2(h2of(r4.y), h2of(r5.y)), __hadd2(h2of(r6.y), h2of(r7.y))));
    float2 fx = __half22float2(tx);
    float2 fy = __half22float2(ty);
    acc.x += fx.x; acc.y += fx.y; acc.z += fy.x; acc.w += fy.y;
}

__global__ void __launch_bounds__(256)
k_gather(int n) {
    int w = (blockIdx.x * 256 + threadIdx.x) >> 5;
    int lane = threadIdx.x & 31;
    if (w >= n) return;
    int d = w;
    int c = lane * 4;

    float sc = g_dis[d];

    // self term in fp32
    uint2 rs = *(const uint2*)&g_h1h[d * HID + c];
    float2 s0 = __half22float2(h2of(rs.x));
    float2 s1 = __half22float2(h2of(rs.y));
    float4 acc = make_float4(s0.x, s0.y, s1.x, s1.y);

    int base = d * ELLW;
    int nb = min(g_cnt[d], ELLW);
    int i = 0;
    if (nb >= 8) {
        int4 sa = *(const int4*)&g_ell[base];
        int4 sb = *(const int4*)&g_ell[base + 4];
        for (; i + 16 <= nb; i += 8) {
            // prefetch next group's indices before consuming current rows
            int4 na = *(const int4*)&g_ell[base + i + 8];
            int4 nb2 = *(const int4*)&g_ell[base + i + 12];
            gat8(acc, sa, sb, c);
            sa = na; sb = nb2;
        }
        gat8(acc, sa, sb, c);   // last full 8-group
        i += 8;
    }
    for (; i + 4 <= nb; i += 4) {
        int4 sa = *(const int4*)&g_ell[base + i];
        uint2 r0 = *(const uint2*)&g_h1h[sa.x * HID + c];
        uint2 r1 = *(const uint2*)&g_h1h[sa.y * HID + c];
        uint2 r2 = *(const uint2*)&g_h1h[sa.z * HID + c];
        uint2 r3 = *(const uint2*)&g_h1h[sa.w * HID + c];
        __half2 tx = __hadd2(__hadd2(h2of(r0.x), h2of(r1.x)), __hadd2(h2of(r2.x), h2of(r3.x)));
        __half2 ty = __hadd2(__hadd2(h2of(r0.y), h2of(r1.y)), __hadd2(h2of(r2.y), h2of(r3.y)));
        float2 fx = __half22float2(tx);
        float2 fy = __half22float2(ty);
        acc.x += fx.x; acc.y += fx.y; acc.z += fy.x; acc.w += fy.y;
    }
    for (; i < nb; i++) {
        int s = g_ell[base + i];
        uint2 r = *(const uint2*)&g_h1h[s * HID + c];
        float2 f0 = __half22float2(h2of(r.x));
        float2 f1 = __half22float2(h2of(r.y));
        acc.x += f0.x; acc.y += f0.y; acc.z += f1.x; acc.w += f1.y;
    }
    __half2 h01 = __floats2half2_rn(acc.x * sc, acc.y * sc);
    __half2 h23 = __floats2half2_rn(acc.z * sc, acc.w * sc);
    uint2 u;
    u.x = *(unsigned*)&h01;
    u.y = *(unsigned*)&h23;
    *(uint2*)&g_aggh[d * HID + c] = u;
    if (lane == 0) g_cnt[d] = 0;   // restore invariant for next replay
}

// ---------------- launch 4: GEMM — split-fp16 MMA + fragment-direct FC epilogue ----------------

__device__ __forceinline__ void ldsm4(uint32_t& r0, uint32_t& r1, uint32_t& r2, uint32_t& r3,
                                      uint32_t addr) {
    asm volatile("ldmatrix.sync.aligned.m8n8.x4.shared.b16 {%0,%1,%2,%3}, [%4];"
        : "=r"(r0), "=r"(r1), "=r"(r2), "=r"(r3) : "r"(addr));
}

__device__ __forceinline__ void mma16816(float* c,
        uint32_t a0, uint32_t a1, uint32_t a2, uint32_t a3,
        uint32_t b0, uint32_t b1) {
    asm volatile("mma.sync.aligned.m16n8k16.row.col.f32.f16.f16.f32 "
        "{%0,%1,%2,%3}, {%4,%5,%6,%7}, {%8,%9}, {%0,%1,%2,%3};"
        : "+f"(c[0]), "+f"(c[1]), "+f"(c[2]), "+f"(c[3])
        : "r"(a0), "r"(a1), "r"(a2), "r"(a3), "r"(b0), "r"(b1));
}

// smem layout (bytes):
//   Wh  [0,      32768)   half[128][128]  W2^T hi, swizzled
//   Wl  [32768,  65536)   half[128][128]  W2^T lo residual
//   Ah  [65536,  81920)   half[64][128]
//   Ps  [81920,  83968)   float[2][64][4] FC partials (per col-half)
//   b2s [83968, 84480), Wfcs [84480,86016), bfcs [86016,86032)
#define SM_WH   0
#define SM_WL   32768
#define SM_AH   65536
#define SM_PS   81920
#define SM_B2   83968
#define SM_WFC  84480
#define SM_BFC  86016
#define SM_TOT  86032

__global__ void __launch_bounds__(256)
k_gemm(const float* __restrict__ W2, const float* __restrict__ b2,
       const float* __restrict__ Wfc, const float* __restrict__ bfc,
       float* __restrict__ out, int n) {
    extern __shared__ char smx[];
    __half* Wh  = (__half*)(smx + SM_WH);
    __half* Wl  = (__half*)(smx + SM_WL);
    __half* Ah  = (__half*)(smx + SM_AH);
    float*  Ps  = (float*)(smx + SM_PS);   // [2][64][4]
    float*  b2s = (float*)(smx + SM_B2);
    float*  Wfcs= (float*)(smx + SM_WFC);
    float*  bfcs= (float*)(smx + SM_BFC);

    int tid = threadIdx.x;
    for (int idx = tid; idx < HID * HID; idx += 256) {
        int k = idx >> 7;
        int nn = idx & 127;
        float w = W2[idx];
        __half wh = __float2half_rn(w);
        __half wl = __float2half_rn(w - __half2float(wh));
        int kc = k >> 3, ko = k & 7;
        int off = nn * 128 + (((kc ^ (nn & 7)) << 3) + ko);
        Wh[off] = wh;
        Wl[off] = wl;
    }
    for (int i = tid; i < HID; i += 256) b2s[i] = b2[i];
    for (int i = tid; i < HID * 3; i += 256) Wfcs[i] = Wfc[i];
    if (tid < 3) bfcs[tid] = bfc[tid];
    __syncthreads();

    int warp = tid >> 5;
    int lane = tid & 31;
    int c = lane * 4;

    uint32_t ah_base = (uint32_t)__cvta_generic_to_shared(Ah);
    uint32_t wh_base = (uint32_t)__cvta_generic_to_shared(Wh);
    uint32_t wl_base = (uint32_t)__cvta_generic_to_shared(Wl);

    int mb = (warp >> 1) * 16;          // M rows mb..mb+15 of the 64-row tile
    int half = warp & 1;                // col-half: 0 -> cols 0..63, 1 -> 64..127
    int nbase = half * 64;
    int ar = mb + (lane & 15);

    for (int d0 = blockIdx.x * 64; d0 < n; d0 += gridDim.x * 64) {
        // ===== phase 1: straight fp16 copy gmem -> swizzled smem =====
        #pragma unroll
        for (int j = 0; j < NB; j++) {
            int r = warp * NB + j;
            int d = d0 + r;
            uint2 u = make_uint2(0u, 0u);
            if (d < n) u = *(const uint2*)&g_aggh[d * HID + c];
            int off = r * 128 + ((((lane >> 1) ^ (r & 7)) << 3) + 4 * (lane & 1));
            *(uint2*)(Ah + off) = u;
        }
        __syncthreads();

        // ===== phase 2: C = Ah*(Wh + Wl) =====
        float C[8][4];
        #pragma unroll
        for (int t = 0; t < 8; t++) {
            C[t][0] = 0.f; C[t][1] = 0.f; C[t][2] = 0.f; C[t][3] = 0.f;
        }
        #pragma unroll
        for (int ks = 0; ks < 8; ks++) {
            int kca = 2 * ks + (lane >> 4);
            uint32_t aoff = (uint32_t)((ar * 128 + ((kca ^ (ar & 7)) << 3)) * 2);
            uint32_t ah0, ah1, ah2, ah3;
            ldsm4(ah0, ah1, ah2, ah3, ah_base + aoff);
            int bn = nbase + (lane & 7) + ((lane >> 4) << 3);
            int kcb = 2 * ks + ((lane >> 3) & 1);
            #pragma unroll
            for (int nt = 0; nt < 4; nt++) {
                int bnn = bn + nt * 16;
                uint32_t boff = (uint32_t)((bnn * 128 + ((kcb ^ (bnn & 7)) << 3)) * 2);
                uint32_t bh0, bh1, bh2, bh3, bl0, bl1, bl2, bl3;
                ldsm4(bh0, bh1, bh2, bh3, wh_base + boff);
                ldsm4(bl0, bl1, bl2, bl3, wl_base + boff);
                mma16816(C[nt * 2 + 0], ah0, ah1, ah2, ah3, bh0, bh1);
                mma16816(C[nt * 2 + 1], ah0, ah1, ah2, ah3, bh2, bh3);
                mma16816(C[nt * 2 + 0], ah0, ah1, ah2, ah3, bl0, bl1);
                mma16816(C[nt * 2 + 1], ah0, ah1, ah2, ah3, bl2, bl3);
            }
        }

        // ===== phase 3: fragment-direct bias+relu+Wfc, per-thread partials =====
        float pa0 = 0.f, pa1 = 0.f, pa2 = 0.f;   // row r0 = mb + (lane>>2)
        float pb0 = 0.f, pb1 = 0.f, pb2 = 0.f;   // row r0 + 8
        #pragma unroll
        for (int t = 0; t < 8; t++) {
            int col = nbase + (lane & 3) * 2 + t * 8;
            float bb0 = b2s[col], bb1 = b2s[col + 1];
            float v00 = fmaxf(C[t][0] + bb0, 0.f);
            float v01 = fmaxf(C[t][1] + bb1, 0.f);
            float v10 = fmaxf(C[t][2] + bb0, 0.f);
            float v11 = fmaxf(C[t][3] + bb1, 0.f);
            float w00 = Wfcs[col * 3 + 0], w01 = Wfcs[col * 3 + 1], w02 = Wfcs[col * 3 + 2];
            float w10 = Wfcs[col * 3 + 3], w11 = Wfcs[col * 3 + 4], w12 = Wfcs[col * 3 + 5];
            pa0 += v00 * w00 + v01 * w10;
            pa1 += v00 * w01 + v01 * w11;
            pa2 += v00 * w02 + v01 * w12;
            pb0 += v10 * w00 + v11 * w10;
            pb1 += v10 * w01 + v11 * w11;
            pb2 += v10 * w02 + v11 * w12;
        }
        // reduce across the 4 lanes sharing a row (lane bits 0-1)
        #pragma unroll
        for (int o = 1; o <= 2; o <<= 1) {
            pa0 += __shfl_xor_sync(0xffffffffu, pa0, o);
            pa1 += __shfl_xor_sync(0xffffffffu, pa1, o);
            pa2 += __shfl_xor_sync(0xffffffffu, pa2, o);
            pb0 += __shfl_xor_sync(0xffffffffu, pb0, o);
            pb1 += __shfl_xor_sync(0xffffffffu, pb1, o);
            pb2 += __shfl_xor_sync(0xffffffffu, pb2, o);
        }
        if ((lane & 3) == 0) {
            int g = lane >> 2;
            int ra = (half * 64 + mb + g) * 4;
            int rb = (half * 64 + mb + 8 + g) * 4;
            Ps[ra + 0] = pa0; Ps[ra + 1] = pa1; Ps[ra + 2] = pa2;
            Ps[rb + 0] = pb0; Ps[rb + 1] = pb1; Ps[rb + 2] = pb2;
        }
        __syncthreads();

        // ===== phase 4: combine col-halves + write out (coalesced 192 floats) =====
        if (tid < 192) {
            int r = tid / 3, j = tid - r * 3;
            int d = d0 + r;
            if (d < n) {
                float v = Ps[r * 4 + j] + Ps[(64 + r) * 4 + j] + bfcs[j];
                out[d * 3 + j] = v;
            }
        }
        __syncthreads();   // Ah/Ps reused next pass
    }
}

// ---------------- launcher (5 launches) ----------------

extern "C" void kernel_launch(void* const* d_in, const int* in_sizes, int n_in,
                              void* d_out, int out_size) {
    const float* x   = (const float*)d_in[0];
    const int*   ei  = (const int*)d_in[1];   // int32 (JAX downcasts int64)
    const float* W1  = (const float*)d_in[2];
    const float* b1  = (const float*)d_in[3];
    const float* W2  = (const float*)d_in[4];
    const float* b2  = (const float*)d_in[5];
    const float* Wfc = (const float*)d_in[6];
    const float* bfc = (const float*)d_in[7];
    float* out = (float*)d_out;

    int n = in_sizes[0] / 3;
    int E = in_sizes[1] / 2;

    k_scat<<<(E / 4 + 255) / 256, 256>>>(ei, E);
    k_prep<<<(n + 255) / 256, 256>>>(x, n);
    k_aggl1<<<(n + 7) / 8, 256>>>(W1, b1, n);
    k_gather<<<(n * 32 + 255) / 256, 256>>>(n);

    cudaFuncSetAttribute(k_gemm, cudaFuncAttributeMaxDynamicSharedMemorySize, SM_TOT);
    k_gemm<<<296, 256, SM_TOT>>>(W2, b2, Wfc, bfc, out, n);
}

// round 17
// speedup vs baseline: 1.0241x; 1.0241x over previous
#include <cuda_runtime.h>
#include <cuda_fp16.h>
#include <stdint.h>

#define NN   100000
#define NE   3200000
#define HID  128
#define ELLW 96      // ELL row width; P(deg >= 96) ~ 1e-18 for Poisson(32)
#define NB   8       // rows per warp in k_gemm tile load

// ---- device scratch ----
__device__ int    g_cnt[NN];           // in-degree; re-zeroed by k_gather each replay
__device__ float  g_dis[NN];           // (deg+1)^{-1/2}
__device__ int    g_ell[NN * ELLW];    // ELL neighbor lists (src ids)
__device__ float  g_xs4[NN * 4];       // {dis*x0, dis*x1, dis*x2, 0}
__device__ __half g_h1h[NN * HID];     // fp16: dis[i] * relu(layer1)
__device__ __half g_aggh[NN * HID];    // fp16 layer-2 aggregate

// ---------------- launch 0: single-pass ELL scatter, 4 edges/thread ----------------

__global__ void k_scat(const int* __restrict__ ei, int E) {
    int e = (blockIdx.x * blockDim.x + threadIdx.x) * 4;
    if (e + 3 < E) {
        int4 s4 = *(const int4*)&ei[e];
        int4 d4 = *(const int4*)&ei[E + e];
        int p0 = atomicAdd(&g_cnt[d4.x], 1);
        if (p0 < ELLW) g_ell[d4.x * ELLW + p0] = s4.x;
        int p1 = atomicAdd(&g_cnt[d4.y], 1);
        if (p1 < ELLW) g_ell[d4.y * ELLW + p1] = s4.y;
        int p2 = atomicAdd(&g_cnt[d4.z], 1);
        if (p2 < ELLW) g_ell[d4.z * ELLW + p2] = s4.z;
        int p3 = atomicAdd(&g_cnt[d4.w], 1);
        if (p3 < ELLW) g_ell[d4.w * ELLW + p3] = s4.w;
    } else {
        for (; e < E; e++) {
            int d = ei[E + e];
            int pos = atomicAdd(&g_cnt[d], 1);
            if (pos < ELLW) g_ell[d * ELLW + pos] = ei[e];
        }
    }
}

// ---------------- launch 1: dis + xs4 ----------------

__global__ void k_prep(const float* __restrict__ x, int n) {
    int i = blockIdx.x * blockDim.x + threadIdx.x;
    if (i < n) {
        float dis = rsqrtf((float)(min(g_cnt[i], ELLW) + 1));
        g_dis[i] = dis;
        float4 v;
        v.x = dis * x[3 * i + 0];
        v.y = dis * x[3 * i + 1];
        v.z = dis * x[3 * i + 2];
        v.w = 0.f;
        *(float4*)&g_xs4[4 * i] = v;
    }
}

// ---------------- launch 2: fused layer-1 agg (warp-per-node, 3 parallel loads) + GEMM ----------------

__global__ void __launch_bounds__(256)
k_aggl1(const float* __restrict__ W1, const float* __restrict__ b1, int n) {
    __shared__ float W1s[3 * HID];
    __shared__ float b1s[HID];
    int tid = threadIdx.x;
    for (int i = tid; i < 3 * HID; i += 256) W1s[i] = W1[i];
    for (int i = tid; i < HID; i += 256) b1s[i] = b1[i];
    __syncthreads();

    int warp = tid >> 5;
    int lane = tid & 31;
    int d = blockIdx.x * 8 + warp;
    if (d >= n) return;

    int base = d * ELLW;
    int nb = min(g_cnt[d], ELLW);
    float sx = 0.f, sy = 0.f, sz = 0.f;
    // ELLW/32 = 3 predicated independent loads, all in flight at once
    #pragma unroll
    for (int t = 0; t < ELLW / 32; t++) {
        int idx = lane + t * 32;
        if (idx < nb) {
            int s = g_ell[base + idx];
            float4 v = *(const float4*)&g_xs4[4 * s];
            sx += v.x; sy += v.y; sz += v.z;
        }
    }
    #pragma unroll
    for (int o = 16; o > 0; o >>= 1) {
        sx += __shfl_xor_sync(0xffffffffu, sx, o);
        sy += __shfl_xor_sync(0xffffffffu, sy, o);
        sz += __shfl_xor_sync(0xffffffffu, sz, o);
    }
    float4 self = *(const float4*)&g_xs4[4 * d];
    float dis = g_dis[d];
    float a0 = (sx + self.x) * dis;
    float a1 = (sy + self.y) * dis;
    float a2 = (sz + self.z) * dis;

    int c = lane * 4;
    float4 o4;
    o4.x = fmaxf(a0 * W1s[c + 0] + a1 * W1s[HID + c + 0] + a2 * W1s[2 * HID + c + 0] + b1s[c + 0], 0.f) * dis;
    o4.y = fmaxf(a0 * W1s[c + 1] + a1 * W1s[HID + c + 1] + a2 * W1s[2 * HID + c + 1] + b1s[c + 1], 0.f) * dis;
    o4.z = fmaxf(a0 * W1s[c + 2] + a1 * W1s[HID + c + 2] + a2 * W1s[2 * HID + c + 2] + b1s[c + 2], 0.f) * dis;
    o4.w = fmaxf(a0 * W1s[c + 3] + a1 * W1s[HID + c + 3] + a2 * W1s[2 * HID + c + 3] + b1s[c + 3], 0.f) * dis;
    __half2 h0 = __floats2half2_rn(o4.x, o4.y);
    __half2 h1 = __floats2half2_rn(o4.z, o4.w);
    uint2 u;
    u.x = *(unsigned*)&h0;
    u.y = *(unsigned*)&h1;
    *(uint2*)&g_h1h[d * HID + c] = u;
}

// ---------------- launch 3: layer-2 gather (R15 body: warp-per-node, HADD2 tree-8, no prefetch) ----------------

__device__ __forceinline__ __half2 h2of(uint32_t w) { return *(__half2*)&w; }

__global__ void __launch_bounds__(256)
k_gather(int n) {
    int w = (blockIdx.x * 256 + threadIdx.x) >> 5;
    int lane = threadIdx.x & 31;
    if (w >= n) return;
    int d = w;
    int c = lane * 4;

    // self term in fp32
    uint2 rs = *(const uint2*)&g_h1h[d * HID + c];
    float2 s0 = __half22float2(h2of(rs.x));
    float2 s1 = __half22float2(h2of(rs.y));
    float4 acc = make_float4(s0.x, s0.y, s1.x, s1.y);

    int base = d * ELLW;
    int nb = min(g_cnt[d], ELLW);
    int i = 0;
    for (; i + 8 <= nb; i += 8) {
        int4 sa = *(const int4*)&g_ell[base + i];
        int4 sb = *(const int4*)&g_ell[base + i + 4];
        uint2 r0 = *(const uint2*)&g_h1h[sa.x * HID + c];
        uint2 r1 = *(const uint2*)&g_h1h[sa.y * HID + c];
        uint2 r2 = *(const uint2*)&g_h1h[sa.z * HID + c];
        uint2 r3 = *(const uint2*)&g_h1h[sa.w * HID + c];
        uint2 r4 = *(const uint2*)&g_h1h[sb.x * HID + c];
        uint2 r5 = *(const uint2*)&g_h1h[sb.y * HID + c];
        uint2 r6 = *(const uint2*)&g_h1h[sb.z * HID + c];
        uint2 r7 = *(const uint2*)&g_h1h[sb.w * HID + c];
        // tree-8 fp16 partial sums (3 roundings/elem before fp32)
        __half2 tx = __hadd2(
            __hadd2(__hadd2(h2of(r0.x), h2of(r1.x)), __hadd2(h2of(r2.x), h2of(r3.x))),
            __hadd2(__hadd2(h2of(r4.x), h2of(r5.x)), __hadd2(h2of(r6.x), h2of(r7.x))));
        __half2 ty = __hadd2(
            __hadd2(__hadd2(h2of(r0.y), h2of(r1.y)), __hadd2(h2of(r2.y), h2of(r3.y))),
            __hadd2(__hadd2(h2of(r4.y), h2of(r5.y)), __hadd2(h2of(r6.y), h2of(r7.y))));
        float2 fx = __half22float2(tx);
        float2 fy = __half22float2(ty);
        acc.x += fx.x; acc.y += fx.y; acc.z += fy.x; acc.w += fy.y;
    }
    for (; i < nb; i++) {
        int s = g_ell[base + i];
        uint2 r = *(const uint2*)&g_h1h[s * HID + c];
        float2 f0 = __half22float2(h2of(r.x));
        float2 f1 = __half22float2(h2of(r.y));
        acc.x += f0.x; acc.y += f0.y; acc.z += f1.x; acc.w += f1.y;
    }
    float sc = g_dis[d];
    __half2 h01 = __floats2half2_rn(acc.x * sc, acc.y * sc);
    __half2 h23 = __floats2half2_rn(acc.z * sc, acc.w * sc);
    uint2 u;
    u.x = *(unsigned*)&h01;
    u.y = *(unsigned*)&h23;
    *(uint2*)&g_aggh[d * HID + c] = u;
    if (lane == 0) g_cnt[d] = 0;   // restore invariant for next replay
}

// ---------------- launch 4: GEMM — split-fp16 MMA + fragment-direct FC epilogue ----------------

__device__ __forceinline__ void ldsm4(uint32_t& r0, uint32_t& r1, uint32_t& r2, uint32_t& r3,
                                      uint32_t addr) {
    asm volatile("ldmatrix.sync.aligned.m8n8.x4.shared.b16 {%0,%1,%2,%3}, [%4];"
        : "=r"(r0), "=r"(r1), "=r"(r2), "=r"(r3) : "r"(addr));
}

__device__ __forceinline__ void mma16816(float* c,
        uint32_t a0, uint32_t a1, uint32_t a2, uint32_t a3,
        uint32_t b0, uint32_t b1) {
    asm volatile("mma.sync.aligned.m16n8k16.row.col.f32.f16.f16.f32 "
        "{%0,%1,%2,%3}, {%4,%5,%6,%7}, {%8,%9}, {%0,%1,%2,%3};"
        : "+f"(c[0]), "+f"(c[1]), "+f"(c[2]), "+f"(c[3])
        : "r"(a0), "r"(a1), "r"(a2), "r"(a3), "r"(b0), "r"(b1));
}

// smem layout (bytes):
//   Wh  [0,      32768)   half[128][128]  W2^T hi, swizzled
//   Wl  [32768,  65536)   half[128][128]  W2^T lo residual
//   Ah  [65536,  81920)   half[64][128]
//   Ps  [81920,  83968)   float[2][64][4] FC partials (per col-half)
//   b2s [83968, 84480), Wfcs [84480,86016), bfcs [86016,86032)
#define SM_WH   0
#define SM_WL   32768
#define SM_AH   65536
#define SM_PS   81920
#define SM_B2   83968
#define SM_WFC  84480
#define SM_BFC  86016
#define SM_TOT  86032

__global__ void __launch_bounds__(256)
k_gemm(const float* __restrict__ W2, const float* __restrict__ b2,
       const float* __restrict__ Wfc, const float* __restrict__ bfc,
       float* __restrict__ out, int n) {
    extern __shared__ char smx[];
    __half* Wh  = (__half*)(smx + SM_WH);
    __half* Wl  = (__half*)(smx + SM_WL);
    __half* Ah  = (__half*)(smx + SM_AH);
    float*  Ps  = (float*)(smx + SM_PS);   // [2][64][4]
    float*  b2s = (float*)(smx + SM_B2);
    float*  Wfcs= (float*)(smx + SM_WFC);
    float*  bfcs= (float*)(smx + SM_BFC);

    int tid = threadIdx.x;
    for (int idx = tid; idx < HID * HID; idx += 256) {
        int k = idx >> 7;
        int nn = idx & 127;
        float w = W2[idx];
        __half wh = __float2half_rn(w);
        __half wl = __float2half_rn(w - __half2float(wh));
        int kc = k >> 3, ko = k & 7;
        int off = nn * 128 + (((kc ^ (nn & 7)) << 3) + ko);
        Wh[off] = wh;
        Wl[off] = wl;
    }
    for (int i = tid; i < HID; i += 256) b2s[i] = b2[i];
    for (int i = tid; i < HID * 3; i += 256) Wfcs[i] = Wfc[i];
    if (tid < 3) bfcs[tid] = bfc[tid];
    __syncthreads();

    int warp = tid >> 5;
    int lane = tid & 31;
    int c = lane * 4;

    uint32_t ah_base = (uint32_t)__cvta_generic_to_shared(Ah);
    uint32_t wh_base = (uint32_t)__cvta_generic_to_shared(Wh);
    uint32_t wl_base = (uint32_t)__cvta_generic_to_shared(Wl);

    int mb = (warp >> 1) * 16;          // M rows mb..mb+15 of the 64-row tile
    int half = warp & 1;                // col-half: 0 -> cols 0..63, 1 -> 64..127
    int nbase = half * 64;
    int ar = mb + (lane & 15);

    for (int d0 = blockIdx.x * 64; d0 < n; d0 += gridDim.x * 64) {
        // ===== phase 1: straight fp16 copy gmem -> swizzled smem =====
        #pragma unroll
        for (int j = 0; j < NB; j++) {
            int r = warp * NB + j;
            int d = d0 + r;
            uint2 u = make_uint2(0u, 0u);
            if (d < n) u = *(const uint2*)&g_aggh[d * HID + c];
            int off = r * 128 + ((((lane >> 1) ^ (r & 7)) << 3) + 4 * (lane & 1));
            *(uint2*)(Ah + off) = u;
        }
        __syncthreads();

        // ===== phase 2: C = Ah*(Wh + Wl) =====
        float C[8][4];
        #pragma unroll
        for (int t = 0; t < 8; t++) {
            C[t][0] = 0.f; C[t][1] = 0.f; C[t][2] = 0.f; C[t][3] = 0.f;
        }
        #pragma unroll
        for (int ks = 0; ks < 8; ks++) {
            int kca = 2 * ks + (lane >> 4);
            uint32_t aoff = (uint32_t)((ar * 128 + ((kca ^ (ar & 7)) << 3)) * 2);
            uint32_t ah0, ah1, ah2, ah3;
            ldsm4(ah0, ah1, ah2, ah3, ah_base + aoff);
            int bn = nbase + (lane & 7) + ((lane >> 4) << 3);
            int kcb = 2 * ks + ((lane >> 3) & 1);
            #pragma unroll
            for (int nt = 0; nt < 4; nt++) {
                int bnn = bn + nt * 16;
                uint32_t boff = (uint32_t)((bnn * 128 + ((kcb ^ (bnn & 7)) << 3)) * 2);
                uint32_t bh0, bh1, bh2, bh3, bl0, bl1, bl2, bl3;
                ldsm4(bh0, bh1, bh2, bh3, wh_base + boff);
                ldsm4(bl0, bl1, bl2, bl3, wl_base + boff);
                mma16816(C[nt * 2 + 0], ah0, ah1, ah2, ah3, bh0, bh1);
                mma16816(C[nt * 2 + 1], ah0, ah1, ah2, ah3, bh2, bh3);
                mma16816(C[nt * 2 + 0], ah0, ah1, ah2, ah3, bl0, bl1);
                mma16816(C[nt * 2 + 1], ah0, ah1, ah2, ah3, bl2, bl3);
            }
        }

        // ===== phase 3: fragment-direct bias+relu+Wfc, per-thread partials =====
        float pa0 = 0.f, pa1 = 0.f, pa2 = 0.f;   // row r0 = mb + (lane>>2)
        float pb0 = 0.f, pb1 = 0.f, pb2 = 0.f;   // row r0 + 8
        #pragma unroll
        for (int t = 0; t < 8; t++) {
            int col = nbase + (lane & 3) * 2 + t * 8;
            float bb0 = b2s[col], bb1 = b2s[col + 1];
            float v00 = fmaxf(C[t][0] + bb0, 0.f);
            float v01 = fmaxf(C[t][1] + bb1, 0.f);
            float v10 = fmaxf(C[t][2] + bb0, 0.f);
            float v11 = fmaxf(C[t][3] + bb1, 0.f);
            float w00 = Wfcs[col * 3 + 0], w01 = Wfcs[col * 3 + 1], w02 = Wfcs[col * 3 + 2];
            float w10 = Wfcs[col * 3 + 3], w11 = Wfcs[col * 3 + 4], w12 = Wfcs[col * 3 + 5];
            pa0 += v00 * w00 + v01 * w10;
            pa1 += v00 * w01 + v01 * w11;
            pa2 += v00 * w02 + v01 * w12;
            pb0 += v10 * w00 + v11 * w10;
            pb1 += v10 * w01 + v11 * w11;
            pb2 += v10 * w02 + v11 * w12;
        }
        // reduce across the 4 lanes sharing a row (lane bits 0-1)
        #pragma unroll
        for (int o = 1; o <= 2; o <<= 1) {
            pa0 += __shfl_xor_sync(0xffffffffu, pa0, o);
            pa1 += __shfl_xor_sync(0xffffffffu, pa1, o);
            pa2 += __shfl_xor_sync(0xffffffffu, pa2, o);
            pb0 += __shfl_xor_sync(0xffffffffu, pb0, o);
            pb1 += __shfl_xor_sync(0xffffffffu, pb1, o);
            pb2 += __shfl_xor_sync(0xffffffffu, pb2, o);
        }
        if ((lane & 3) == 0) {
            int g = lane >> 2;
            int ra = (half * 64 + mb + g) * 4;
            int rb = (half * 64 + mb + 8 + g) * 4;
            Ps[ra + 0] = pa0; Ps[ra + 1] = pa1; Ps[ra + 2] = pa2;
            Ps[rb + 0] = pb0; Ps[rb + 1] = pb1; Ps[rb + 2] = pb2;
        }
        __syncthreads();

        // ===== phase 4: combine col-halves + write out (coalesced 192 floats) =====
        if (tid < 192) {
            int r = tid / 3, j = tid - r * 3;
            int d = d0 + r;
            if (d < n) {
                float v = Ps[r * 4 + j] + Ps[(64 + r) * 4 + j] + bfcs[j];
                out[d * 3 + j] = v;
            }
        }
        __syncthreads();   // Ah/Ps reused next pass
    }
}

// ---------------- launcher (5 launches) ----------------

extern "C" void kernel_launch(void* const* d_in, const int* in_sizes, int n_in,
                              void* d_out, int out_size) {
    const float* x   = (const float*)d_in[0];
    const int*   ei  = (const int*)d_in[1];   // int32 (JAX downcasts int64)
    const float* W1  = (const float*)d_in[2];
    const float* b1  = (const float*)d_in[3];
    const float* W2  = (const float*)d_in[4];
    const float* b2  = (const float*)d_in[5];
    const float* Wfc = (const float*)d_in[6];
    const float* bfc = (const float*)d_in[7];
    float* out = (float*)d_out;

    int n = in_sizes[0] / 3;
    int E = in_sizes[1] / 2;

    k_scat<<<(E / 4 + 255) / 256, 256>>>(ei, E);
    k_prep<<<(n + 255) / 256, 256>>>(x, n);
    k_aggl1<<<(n + 7) / 8, 256>>>(W1, b1, n);
    k_gather<<<(n * 32 + 255) / 256, 256>>>(n);

    cudaFuncSetAttribute(k_gemm, cudaFuncAttributeMaxDynamicSharedMemorySize, SM_TOT);
    k_gemm<<<296, 256, SM_TOT>>>(W2, b2, Wfc, bfc, out, n);
}